// round 1
// baseline (speedup 1.0000x reference)
#include <cuda_runtime.h>

// ----------------------------------------------------------------------------
// Kernel 1: bulk copy memory -> new_memory (float4 vectorized, grid-stride)
// ----------------------------------------------------------------------------
__global__ void copy_mem_kernel(const float4* __restrict__ src,
                                float4* __restrict__ dst,
                                long long n4) {
    long long i = (long long)blockIdx.x * blockDim.x + threadIdx.x;
    long long stride = (long long)gridDim.x * blockDim.x;
    for (; i < n4; i += stride) {
        dst[i] = src[i];
    }
}

// ----------------------------------------------------------------------------
// Kernel 2: momentum update of positive rows.
// One block per batch element b, D threads (D=128).
//   w = 0.5*memory[y[b]] + 0.5*x[b];  w /= ||w||;  new_memory[y[b]] = w
// Duplicate labels: JAX .at[y].set -> last occurrence wins, so only the
// last b with a given y[b] writes.
// ----------------------------------------------------------------------------
__global__ void update_pos_kernel(const float* __restrict__ x,
                                  const float* __restrict__ memory,
                                  const int* __restrict__ y,
                                  float* __restrict__ new_memory,
                                  int B, int D) {
    int b = blockIdx.x;
    int t = threadIdx.x;          // blockDim.x == D (multiple of 32)
    int row = y[b];

    // last-occurrence-wins check (B is tiny: 256)
    bool is_last = true;
    for (int b2 = b + 1; b2 < B; b2++) {
        if (y[b2] == row) { is_last = false; break; }
    }

    float w = 0.5f * memory[(long long)row * D + t] + 0.5f * x[(long long)b * D + t];

    // block reduction of w*w
    float s = w * w;
    #pragma unroll
    for (int o = 16; o > 0; o >>= 1)
        s += __shfl_down_sync(0xffffffffu, s, o);

    __shared__ float sh[32];
    int lane = t & 31, wid = t >> 5;
    if (lane == 0) sh[wid] = s;
    __syncthreads();
    if (t == 0) {
        float tot = 0.0f;
        int nw = blockDim.x >> 5;
        for (int i = 0; i < nw; i++) tot += sh[i];
        sh[0] = tot;
    }
    __syncthreads();

    float inv = 1.0f / sqrtf(sh[0]);
    if (is_last) {
        new_memory[(long long)row * D + t] = w * inv;
    }
}

// ----------------------------------------------------------------------------
// Kernel 3: gather-dot scores (uses OLD memory).
// One warp computes one (b,k) dot product; each warp batches ITER=4 rows to
// get memory-level parallelism on the 512B row loads.
// Block: 256 threads (8 warps). grid = (ceil(Kp1/(8*ITER)), B).
// x[b] staged in shared as float4.
// ----------------------------------------------------------------------------
#define SCORE_ITER 4

__global__ void scores_kernel(const float* __restrict__ x,
                              const float* __restrict__ memory,
                              const int* __restrict__ idx,
                              float* __restrict__ out,
                              int Kp1, int D, float invT) {
    int b = blockIdx.y;
    extern __shared__ float4 xs[];          // D/4 float4
    int tid  = threadIdx.x;
    int d4   = D >> 2;                      // 32 for D=128
    if (tid < d4) xs[tid] = ((const float4*)(x + (long long)b * D))[tid];
    __syncthreads();

    int lane = tid & 31;
    int warp = tid >> 5;
    int warps_per_block = blockDim.x >> 5;  // 8
    int k0 = (blockIdx.x * warps_per_block + warp) * SCORE_ITER;

    const int* idxrow = idx + (long long)b * Kp1;

    // Phase 1: gather indices (uniform per warp — broadcast loads)
    int  r[SCORE_ITER];
    bool valid[SCORE_ITER];
    #pragma unroll
    for (int j = 0; j < SCORE_ITER; j++) {
        int k = k0 + j;
        valid[j] = (k < Kp1);
        r[j] = valid[j] ? idxrow[k] : 0;
    }

    // Phase 2: issue all row loads back-to-back (MLP=4 per warp per d-chunk)
    // D=128 -> d4=32 -> single chunk; generic loop kept for safety.
    float s[SCORE_ITER];
    #pragma unroll
    for (int j = 0; j < SCORE_ITER; j++) s[j] = 0.0f;

    for (int dbase = 0; dbase < d4; dbase += 32) {
        float4 xv = xs[dbase + lane];
        float4 v[SCORE_ITER];
        #pragma unroll
        for (int j = 0; j < SCORE_ITER; j++) {
            v[j] = valid[j]
                 ? ((const float4*)(memory + (long long)r[j] * D))[dbase + lane]
                 : make_float4(0.f, 0.f, 0.f, 0.f);
        }
        #pragma unroll
        for (int j = 0; j < SCORE_ITER; j++) {
            s[j] += v[j].x * xv.x + v[j].y * xv.y + v[j].z * xv.z + v[j].w * xv.w;
        }
    }

    // Phase 3: warp reduce + store
    #pragma unroll
    for (int j = 0; j < SCORE_ITER; j++) {
        float t = s[j];
        #pragma unroll
        for (int o = 16; o > 0; o >>= 1)
            t += __shfl_down_sync(0xffffffffu, t, o);
        if (lane == 0 && valid[j]) {
            out[(long long)b * Kp1 + (k0 + j)] = t * invT;
        }
    }
}

// ----------------------------------------------------------------------------
// Launch. Inputs (metadata order): x [B,D] f32, memory [N,D] f32,
// y [B] i32, idx [B,K+1] i32. Output: out [B,K+1] then new_memory [N,D].
// ----------------------------------------------------------------------------
extern "C" void kernel_launch(void* const* d_in, const int* in_sizes, int n_in,
                              void* d_out, int out_size) {
    const float* x      = (const float*)d_in[0];
    const float* memory = (const float*)d_in[1];
    const int*   y      = (const int*)d_in[2];
    const int*   idx    = (const int*)d_in[3];

    int B   = in_sizes[2];               // 256
    int D   = in_sizes[0] / B;           // 128
    int Kp1 = in_sizes[3] / B;           // 4097
    long long ND = (long long)in_sizes[1];  // N*D = 128,000,000

    float* out_scores = (float*)d_out;
    float* new_memory = (float*)d_out + (long long)in_sizes[3];

    const float invT = 1.0f / 0.07f;

    // 1) bulk copy memory -> new_memory
    {
        long long n4 = ND >> 2;                  // float4 count
        int threads = 256;
        long long want = (n4 + threads - 1) / threads;
        int blocks = (want > 262144) ? 262144 : (int)want;
        copy_mem_kernel<<<blocks, threads>>>((const float4*)memory,
                                             (float4*)new_memory, n4);
    }

    // 2) scatter momentum update (after copy: same-stream ordering)
    update_pos_kernel<<<B, D>>>(x, memory, y, new_memory, B, D);

    // 3) gather-dot scores (reads OLD memory — independent of 1/2)
    {
        int threads = 256;
        int warps_per_block = threads / 32;
        int kpb = warps_per_block * SCORE_ITER;      // 32 k per block
        dim3 grid((Kp1 + kpb - 1) / kpb, B);
        size_t shmem = (size_t)(D / 4) * sizeof(float4);
        scores_kernel<<<grid, threads, shmem>>>(x, memory, idx, out_scores,
                                                Kp1, D, invT);
    }
}

// round 2
// speedup vs baseline: 1.1099x; 1.1099x over previous
#include <cuda_runtime.h>

// Scratch (module-static, allowed): inverted index over score entries.
// head[row] -> first entry id (or -1). entries[eid] = (next << 32) | (b<<13 | k).
// eid == b*Kp1 + k, which is also the output offset.
#define MAX_N (1 << 20)        // >= 1,000,000 rows
#define MAX_E (1 << 21)        // >= 1,048,832 entries
__device__ int                g_head[MAX_N];
__device__ unsigned long long g_entries[MAX_E];

// ----------------------------------------------------------------------------
// Kernel A: reset heads to -1 (must run every launch; graph-replay safe)
// ----------------------------------------------------------------------------
__global__ void init_head_kernel(int n) {
    int i = blockIdx.x * blockDim.x + threadIdx.x;
    int stride = gridDim.x * blockDim.x;
    for (; i < n; i += stride) g_head[i] = -1;
}

// ----------------------------------------------------------------------------
// Kernel B: bin entries into per-row chains.
// grid = (ceil(Kp1/256), B). eid = b*Kp1+k. Sequential entry writes,
// atomicExch on 4MB head array (L2-resident).
// ----------------------------------------------------------------------------
__global__ void bin_kernel(const int* __restrict__ idx, int Kp1) {
    int k = blockIdx.x * blockDim.x + threadIdx.x;
    int b = blockIdx.y;
    if (k >= Kp1) return;
    int eid = b * Kp1 + k;
    int row = idx[eid];
    int prev = atomicExch(&g_head[row], eid);
    g_entries[eid] = ((unsigned long long)(unsigned int)prev << 32)
                   | (unsigned int)((b << 13) | k);
}

// ----------------------------------------------------------------------------
// Kernel C: fused copy + scores.
// One warp per row (32 lanes x float4 = 512B). While the row is in registers,
// walk its entry chain and compute dot(row, x[b]) for every (b,k) that
// references it. x (128KB) stays L2-hot. 4 rows per warp iteration for MLP.
// ----------------------------------------------------------------------------
#define ROWS_PER_WARP 4

__global__ void fused_copy_score_kernel(const float4* __restrict__ mem4,
                                        float4* __restrict__ dst4,
                                        const float4* __restrict__ x4,
                                        float* __restrict__ out,
                                        int N, int Kp1, float invT) {
    int lane = threadIdx.x & 31;
    long long warp_id = ((long long)blockIdx.x * blockDim.x + threadIdx.x) >> 5;
    long long nwarps  = ((long long)gridDim.x * blockDim.x) >> 5;

    for (long long r0 = warp_id * ROWS_PER_WARP; r0 < N;
         r0 += nwarps * ROWS_PER_WARP) {

        float4 v[ROWS_PER_WARP];
        int    hd[ROWS_PER_WARP];
        // Phase 1: issue all independent loads (row data + chain heads)
        #pragma unroll
        for (int j = 0; j < ROWS_PER_WARP; j++) {
            long long r = r0 + j;
            if (r < N) v[j] = mem4[r * 32 + lane];
        }
        #pragma unroll
        for (int j = 0; j < ROWS_PER_WARP; j++) {
            long long r = r0 + j;
            hd[j] = (r < N) ? g_head[r] : -1;
        }
        // Phase 2: store copies
        #pragma unroll
        for (int j = 0; j < ROWS_PER_WARP; j++) {
            long long r = r0 + j;
            if (r < N) dst4[r * 32 + lane] = v[j];
        }
        // Phase 3: walk chains (avg ~1 entry per row)
        #pragma unroll
        for (int j = 0; j < ROWS_PER_WARP; j++) {
            unsigned int e = (unsigned int)hd[j];
            while (e != 0xFFFFFFFFu) {
                unsigned long long ent = g_entries[e];   // warp-broadcast load
                unsigned int bk = (unsigned int)ent;
                int b = bk >> 13;
                float4 xv = x4[b * 32 + lane];           // L2 hit (x is 128KB)
                float s = v[j].x * xv.x + v[j].y * xv.y
                        + v[j].z * xv.z + v[j].w * xv.w;
                #pragma unroll
                for (int o = 16; o > 0; o >>= 1)
                    s += __shfl_down_sync(0xffffffffu, s, o);
                if (lane == 0) out[e] = s * invT;        // out index == eid
                e = (unsigned int)(ent >> 32);
            }
        }
    }
}

// ----------------------------------------------------------------------------
// Kernel D: momentum update of positive rows (after copy).
// ----------------------------------------------------------------------------
__global__ void update_pos_kernel(const float* __restrict__ x,
                                  const float* __restrict__ memory,
                                  const int* __restrict__ y,
                                  float* __restrict__ new_memory,
                                  int B, int D) {
    int b = blockIdx.x;
    int t = threadIdx.x;          // blockDim.x == D (128)
    int row = y[b];

    // JAX .at[y].set semantics: last occurrence wins
    bool is_last = true;
    for (int b2 = b + 1; b2 < B; b2++)
        if (y[b2] == row) { is_last = false; break; }

    float w = 0.5f * memory[(long long)row * D + t]
            + 0.5f * x[(long long)b * D + t];

    float s = w * w;
    #pragma unroll
    for (int o = 16; o > 0; o >>= 1)
        s += __shfl_down_sync(0xffffffffu, s, o);

    __shared__ float sh[32];
    int lane = t & 31, wid = t >> 5;
    if (lane == 0) sh[wid] = s;
    __syncthreads();
    if (t == 0) {
        float tot = 0.0f;
        int nw = blockDim.x >> 5;
        for (int i = 0; i < nw; i++) tot += sh[i];
        sh[0] = tot;
    }
    __syncthreads();

    float inv = rsqrtf(sh[0]);
    // exact match to reference's w / sqrt(sum): use 1/sqrt then multiply is
    // within fp32 noise; use division for tighter match
    inv = 1.0f / sqrtf(sh[0]);
    if (is_last)
        new_memory[(long long)row * D + t] = w * inv;
}

// ----------------------------------------------------------------------------
// Launch. Inputs: x [B,D] f32, memory [N,D] f32, y [B] i32, idx [B,K+1] i32.
// Output: out [B,K+1] f32 then new_memory [N,D] f32.
// ----------------------------------------------------------------------------
extern "C" void kernel_launch(void* const* d_in, const int* in_sizes, int n_in,
                              void* d_out, int out_size) {
    const float* x      = (const float*)d_in[0];
    const float* memory = (const float*)d_in[1];
    const int*   y      = (const int*)d_in[2];
    const int*   idx    = (const int*)d_in[3];

    int B   = in_sizes[2];                  // 256
    int D   = in_sizes[0] / B;              // 128
    int Kp1 = in_sizes[3] / B;              // 4097
    int N   = in_sizes[1] / D;              // 1,000,000

    float* out_scores = (float*)d_out;
    float* new_memory = (float*)d_out + (long long)in_sizes[3];

    const float invT = 1.0f / 0.07f;

    // A) reset chain heads
    init_head_kernel<<<2048, 256>>>(N);

    // B) bin score entries by memory row
    {
        dim3 grid((Kp1 + 255) / 256, B);
        bin_kernel<<<grid, 256>>>(idx, Kp1);
    }

    // C) fused copy + scores
    {
        int threads = 256;                  // 8 warps
        int blocks  = 2048;                 // 16384 warps, ~16 row-iterations
        fused_copy_score_kernel<<<blocks, threads>>>(
            (const float4*)memory, (float4*)new_memory,
            (const float4*)x, out_scores, N, Kp1, invT);
    }

    // D) momentum update of positive rows (must follow the copy)
    update_pos_kernel<<<B, D>>>(x, memory, y, new_memory, B, D);
}

// round 3
// speedup vs baseline: 1.1770x; 1.0604x over previous
#include <cuda_runtime.h>

// Inverted index scratch. head[row] -> first eid (-1 if none).
// g_next[eid] -> next eid in chain (-1 terminator). eid = b*Kp1 + k, which is
// simultaneously the output offset; b and k are recovered arithmetically.
#define MAX_N (1 << 20)        // >= 1,000,000 rows
#define MAX_E (1 << 21)        // >= 1,048,832 entries
__device__ int g_head[MAX_N];
__device__ int g_next[MAX_E];

// ----------------------------------------------------------------------------
// Kernel A: reset heads to -1 (runs every launch; graph-replay safe)
// ----------------------------------------------------------------------------
__global__ void init_head_kernel(int n) {
    int i = blockIdx.x * blockDim.x + threadIdx.x;
    int stride = gridDim.x * blockDim.x;
    for (; i < n; i += stride) g_head[i] = -1;
}

// ----------------------------------------------------------------------------
// Kernel B: bin score entries into per-row chains. 4B per entry.
// ----------------------------------------------------------------------------
__global__ void bin_kernel(const int* __restrict__ idx, int Kp1) {
    int k = blockIdx.x * blockDim.x + threadIdx.x;
    int b = blockIdx.y;
    if (k >= Kp1) return;
    int eid = b * Kp1 + k;
    int row = idx[eid];
    g_next[eid] = atomicExch(&g_head[row], eid);
}

// ----------------------------------------------------------------------------
// Kernel C: fused copy + scores + positive momentum update.
// One warp per row (32 lanes x float4 = 512B). While the row is in registers:
//  - walk its entry chain: dot(old_row, x[b]) -> out[eid]
//  - track posb = max{b : k==0} (idx[:,0]==y, so k==0 entries ARE the y-hits;
//    max b == last occurrence == JAX scatter semantics)
//  - store either the plain copy or the normalized momentum update.
// Empty rows (head==-1, ~35%) take a straight-copy fast path.
// ----------------------------------------------------------------------------
#define ROWS_PER_WARP 4

__global__ void fused_copy_score_kernel(const float4* __restrict__ mem4,
                                        float4* __restrict__ dst4,
                                        const float4* __restrict__ x4,
                                        float* __restrict__ out,
                                        int N, int Kp1, float invT) {
    int lane = threadIdx.x & 31;
    long long warp_id = ((long long)blockIdx.x * blockDim.x + threadIdx.x) >> 5;
    long long nwarps  = ((long long)gridDim.x * blockDim.x) >> 5;

    for (long long r0 = warp_id * ROWS_PER_WARP; r0 < N;
         r0 += nwarps * ROWS_PER_WARP) {

        float4 v[ROWS_PER_WARP];
        int    hd[ROWS_PER_WARP];

        // Phase 1: batch all independent loads (row data + chain heads)
        #pragma unroll
        for (int j = 0; j < ROWS_PER_WARP; j++) {
            long long r = r0 + j;
            if (r < N) v[j] = mem4[r * 32 + lane];
        }
        #pragma unroll
        for (int j = 0; j < ROWS_PER_WARP; j++) {
            long long r = r0 + j;
            hd[j] = (r < N) ? g_head[r] : -1;
        }

        // Phase 2: fast-path stores for rows with no score entries
        #pragma unroll
        for (int j = 0; j < ROWS_PER_WARP; j++) {
            long long r = r0 + j;
            if (r < N && hd[j] < 0) dst4[r * 32 + lane] = v[j];
        }

        // Phase 3: chain walk + conditional update for the rest
        #pragma unroll
        for (int j = 0; j < ROWS_PER_WARP; j++) {
            long long r = r0 + j;
            if (r >= N || hd[j] < 0) continue;

            int posb = -1;
            int e = hd[j];
            while (e >= 0) {
                // b = e / Kp1 (compile-time magic for the common case)
                unsigned int ue = (unsigned int)e;
                unsigned int b = (Kp1 == 4097) ? (ue / 4097u)
                                               : (ue / (unsigned int)Kp1);
                int k = e - (int)b * Kp1;
                float4 xv = x4[b * 32 + lane];           // L2-resident (128KB)
                float s = v[j].x * xv.x + v[j].y * xv.y
                        + v[j].z * xv.z + v[j].w * xv.w;
                #pragma unroll
                for (int o = 16; o > 0; o >>= 1)
                    s += __shfl_down_sync(0xffffffffu, s, o);
                if (lane == 0) out[e] = s * invT;
                if (k == 0) posb = max(posb, (int)b);
                e = g_next[e];                           // warp-broadcast load
            }

            float4 w = v[j];
            if (posb >= 0) {
                // momentum update + L2 normalize (uses OLD row, already in regs)
                float4 xv = x4[posb * 32 + lane];
                w.x = 0.5f * w.x + 0.5f * xv.x;
                w.y = 0.5f * w.y + 0.5f * xv.y;
                w.z = 0.5f * w.z + 0.5f * xv.z;
                w.w = 0.5f * w.w + 0.5f * xv.w;
                float s = w.x * w.x + w.y * w.y + w.z * w.z + w.w * w.w;
                #pragma unroll
                for (int o = 16; o > 0; o >>= 1)
                    s += __shfl_xor_sync(0xffffffffu, s, o);
                float inv = 1.0f / sqrtf(s);
                w.x *= inv; w.y *= inv; w.z *= inv; w.w *= inv;
            }
            dst4[r * 32 + lane] = w;
        }
    }
}

// ----------------------------------------------------------------------------
// Launch. Inputs: x [B,D] f32, memory [N,D] f32, y [B] i32, idx [B,K+1] i32.
// Output: out [B,K+1] f32 then new_memory [N,D] f32.
// ----------------------------------------------------------------------------
extern "C" void kernel_launch(void* const* d_in, const int* in_sizes, int n_in,
                              void* d_out, int out_size) {
    const float* x      = (const float*)d_in[0];
    const float* memory = (const float*)d_in[1];
    const int*   idx    = (const int*)d_in[3];

    int B   = in_sizes[2];                  // 256
    int D   = in_sizes[0] / B;              // 128
    int Kp1 = in_sizes[3] / B;              // 4097
    int N   = in_sizes[1] / D;              // 1,000,000

    float* out_scores = (float*)d_out;
    float* new_memory = (float*)d_out + (long long)in_sizes[3];

    const float invT = 1.0f / 0.07f;

    // A) reset chain heads
    init_head_kernel<<<2048, 256>>>(N);

    // B) bin score entries by memory row
    {
        dim3 grid((Kp1 + 255) / 256, B);
        bin_kernel<<<grid, 256>>>(idx, Kp1);
    }

    // C) fused copy + scores + positive update
    {
        int threads = 256;                  // 8 warps/block
        int blocks  = 2368;                 // 16 * 148 SMs
        fused_copy_score_kernel<<<blocks, threads>>>(
            (const float4*)memory, (float4*)new_memory,
            (const float4*)x, out_scores, N, Kp1, invT);
    }
}

// round 5
// speedup vs baseline: 1.1899x; 1.0109x over previous
#include <cuda_runtime.h>

// Inverted index scratch. g_head[row] -> first eid (-1 if none).
// g_next[eid] -> next eid (-1 terminator). eid = b*Kp1 + k == output offset.
#define MAX_N (1 << 20)        // >= 1,000,000 rows
#define MAX_E (1 << 21)        // >= 1,048,832 entries
__device__ int g_head[MAX_N];
__device__ int g_next[MAX_E];

// ----------------------------------------------------------------------------
// Kernel A: reset heads to -1, vectorized int4.
// ----------------------------------------------------------------------------
__global__ void init_head_kernel(int n4) {
    int i = blockIdx.x * blockDim.x + threadIdx.x;
    int stride = gridDim.x * blockDim.x;
    int4 mone = make_int4(-1, -1, -1, -1);
    int4* p = (int4*)g_head;
    for (; i < n4; i += stride) p[i] = mone;
}

// ----------------------------------------------------------------------------
// Kernel B: bin score entries into per-row chains.
// ----------------------------------------------------------------------------
__global__ void bin_kernel(const int* __restrict__ idx, int Kp1) {
    int k = blockIdx.x * blockDim.x + threadIdx.x;
    int b = blockIdx.y;
    if (k >= Kp1) return;
    int eid = b * Kp1 + k;
    int row = idx[eid];
    g_next[eid] = atomicExch(&g_head[row], eid);
}

// ----------------------------------------------------------------------------
// Kernel C: fused copy + scores + positive momentum update.
// One warp per 8 rows. Copy is a pure unconditional load/store stream
// (chain state never gates it). Chain work is batched: first entries of all
// 8 rows are processed with full ILP (8 parallel dots, 8 interleaved shfl
// reductions); longer chains (rare, Poisson lambda~1.05) take a tail loop.
// The ~256 rows hit by the momentum update get an overwriting second store
// (same thread, program order -> correct final value).
// ----------------------------------------------------------------------------
#define RPW 8

template <int KP1C>
__global__ void fused_copy_score_kernel(const float4* __restrict__ mem4,
                                        float4* __restrict__ dst4,
                                        const float4* __restrict__ x4,
                                        float* __restrict__ out,
                                        int N, int Kp1_rt, float invT) {
    const int Kp1 = (KP1C > 0) ? KP1C : Kp1_rt;
    int lane = threadIdx.x & 31;
    int wg = (blockIdx.x * blockDim.x + threadIdx.x) >> 5;
    int r0 = wg * RPW;
    if (r0 >= N) return;

    // ---- Pure copy stream: batch loads, batch stores ----
    float4 v[RPW];
    int hd[RPW];
    #pragma unroll
    for (int j = 0; j < RPW; j++) {
        int r = r0 + j;
        if (r < N) v[j] = mem4[(long long)r * 32 + lane];
    }
    #pragma unroll
    for (int j = 0; j < RPW; j++) {
        int r = r0 + j;
        hd[j] = (r < N) ? g_head[r] : -1;
    }
    #pragma unroll
    for (int j = 0; j < RPW; j++) {
        int r = r0 + j;
        if (r < N) dst4[(long long)r * 32 + lane] = v[j];
    }

    // ---- Early out only if EVERY row in the group has no entries ----
    // AND of all heads == -1 iff all heads are -1 (all bits set).
    int all = -1;
    #pragma unroll
    for (int j = 0; j < RPW; j++) all &= hd[j];
    if (all == -1) return;

    int posb[RPW];
    #pragma unroll
    for (int j = 0; j < RPW; j++) posb[j] = -1;

    // ---- First entries: batched, full ILP ----
    int e[RPW], nxt[RPW];
    float s[RPW];
    #pragma unroll
    for (int j = 0; j < RPW; j++) {
        e[j] = hd[j];
        nxt[j] = (e[j] >= 0) ? g_next[e[j]] : -1;
    }
    #pragma unroll
    for (int j = 0; j < RPW; j++) {
        if (e[j] >= 0) {
            unsigned int b = (unsigned int)e[j] / (unsigned int)Kp1;
            float4 xv = x4[b * 32 + lane];               // L1/L2-resident
            s[j] = v[j].x * xv.x + v[j].y * xv.y
                 + v[j].z * xv.z + v[j].w * xv.w;
        } else {
            s[j] = 0.0f;
        }
    }
    // 8 interleaved warp reductions
    #pragma unroll
    for (int o = 16; o > 0; o >>= 1) {
        #pragma unroll
        for (int j = 0; j < RPW; j++) {
            s[j] += __shfl_xor_sync(0xffffffffu, s[j], o);
        }
    }
    #pragma unroll
    for (int j = 0; j < RPW; j++) {
        if (e[j] >= 0) {
            unsigned int b = (unsigned int)e[j] / (unsigned int)Kp1;
            int k = e[j] - (int)b * Kp1;
            if (lane == 0) out[e[j]] = s[j] * invT;
            if (k == 0) posb[j] = max(posb[j], (int)b);
        }
    }

    // ---- Continuation for chains of length >= 2 (rare) ----
    #pragma unroll
    for (int j = 0; j < RPW; j++) {
        int ee = nxt[j];
        while (ee >= 0) {
            unsigned int b = (unsigned int)ee / (unsigned int)Kp1;
            int k = ee - (int)b * Kp1;
            float4 xv = x4[b * 32 + lane];
            float ss = v[j].x * xv.x + v[j].y * xv.y
                     + v[j].z * xv.z + v[j].w * xv.w;
            #pragma unroll
            for (int o = 16; o > 0; o >>= 1)
                ss += __shfl_xor_sync(0xffffffffu, ss, o);
            if (lane == 0) out[ee] = ss * invT;
            if (k == 0) posb[j] = max(posb[j], (int)b);
            ee = g_next[ee];
        }
    }

    // ---- Momentum update overwrite (~256 rows total across the grid) ----
    #pragma unroll
    for (int j = 0; j < RPW; j++) {
        if (posb[j] >= 0) {
            int r = r0 + j;
            float4 xv = x4[posb[j] * 32 + lane];
            float4 w;
            w.x = 0.5f * v[j].x + 0.5f * xv.x;
            w.y = 0.5f * v[j].y + 0.5f * xv.y;
            w.z = 0.5f * v[j].z + 0.5f * xv.z;
            w.w = 0.5f * v[j].w + 0.5f * xv.w;
            float ss = w.x * w.x + w.y * w.y + w.z * w.z + w.w * w.w;
            #pragma unroll
            for (int o = 16; o > 0; o >>= 1)
                ss += __shfl_xor_sync(0xffffffffu, ss, o);
            float inv = 1.0f / sqrtf(ss);
            w.x *= inv; w.y *= inv; w.z *= inv; w.w *= inv;
            dst4[(long long)r * 32 + lane] = w;
        }
    }
}

// ----------------------------------------------------------------------------
// Launch. Inputs: x [B,D] f32, memory [N,D] f32, y [B] i32, idx [B,K+1] i32.
// Output: out [B,K+1] f32 then new_memory [N,D] f32.
// ----------------------------------------------------------------------------
extern "C" void kernel_launch(void* const* d_in, const int* in_sizes, int n_in,
                              void* d_out, int out_size) {
    const float* x      = (const float*)d_in[0];
    const float* memory = (const float*)d_in[1];
    const int*   idx    = (const int*)d_in[3];

    int B   = in_sizes[2];                  // 256
    int D   = in_sizes[0] / B;              // 128
    int Kp1 = in_sizes[3] / B;              // 4097
    int N   = in_sizes[1] / D;              // 1,000,000

    float* out_scores = (float*)d_out;
    float* new_memory = (float*)d_out + (long long)in_sizes[3];

    const float invT = 1.0f / 0.07f;

    // A) reset chain heads (int4-vectorized)
    {
        int n4 = (N + 3) / 4;
        int threads = 256;
        int blocks = (n4 + threads - 1) / threads;
        if (blocks > 4096) blocks = 4096;
        init_head_kernel<<<blocks, threads>>>(n4);
    }

    // B) bin score entries by memory row
    {
        dim3 grid((Kp1 + 255) / 256, B);
        bin_kernel<<<grid, 256>>>(idx, Kp1);
    }

    // C) fused copy + scores + positive update (one-shot grid, 8 rows/warp)
    {
        int threads = 256;                  // 8 warps/block
        int rows_per_block = (threads / 32) * RPW;   // 64
        int blocks = (N + rows_per_block - 1) / rows_per_block;
        if (Kp1 == 4097) {
            fused_copy_score_kernel<4097><<<blocks, threads>>>(
                (const float4*)memory, (float4*)new_memory,
                (const float4*)x, out_scores, N, Kp1, invT);
        } else {
            fused_copy_score_kernel<0><<<blocks, threads>>>(
                (const float4*)memory, (float4*)new_memory,
                (const float4*)x, out_scores, N, Kp1, invT);
        }
    }
}